// round 16
// baseline (speedup 1.0000x reference)
#include <cuda_runtime.h>
#include <math.h>

// ---------------- problem constants ----------------
#define BB 64
#define TT 256
#define GG 66
#define DCC 128
#define HCC 384
#define LHH 512
#define HH 256
#define H44 1024
#define ST_START 64
#define ST_STOP 65
#define BT (BB*TT)
#define LSTM_BLOCKS 128

// ---------------- packed fp32x2 helpers (sm_100+) ----------------
__device__ __forceinline__ void ffma2(unsigned long long& acc,
                                      unsigned long long a, unsigned long long b) {
    asm("fma.rn.f32x2 %0, %1, %2, %0;" : "+l"(acc) : "l"(a), "l"(b));
}
__device__ __forceinline__ unsigned long long dup2(float x) {
    unsigned long long r;
    asm("mov.b64 %0, {%1, %1};" : "=l"(r) : "f"(x));
    return r;
}
__device__ __forceinline__ void unpk2(unsigned long long v, float& lo, float& hi) {
    asm("mov.b64 {%0, %1}, %2;" : "=f"(lo), "=f"(hi) : "l"(v));
}

// ---------------- acquire/release flag helpers ----------------
__device__ __forceinline__ unsigned ld_acq(const unsigned* p) {
    unsigned v;
    asm volatile("ld.global.acquire.gpu.u32 %0, [%1];" : "=r"(v) : "l"(p) : "memory");
    return v;
}
__device__ __forceinline__ void st_rel(unsigned* p, unsigned v) {
    asm volatile("st.global.release.gpu.u32 [%0], %1;" :: "l"(p), "r"(v) : "memory");
}

// ---------------- scratch (__device__ globals; no allocation allowed) -------
__device__ float g_cwin[(long)BT*384];
__device__ float g_cwt[HCC*384];
__device__ float g_q[(long)BT*512];
__device__ float g_kv[(long)BT*512];
__device__ float g_sc[(long)BT*256];
__device__ float g_x0[(long)BT*512];
__device__ float g_x1[(long)BT*512];
__device__ float g_x2[(long)BT*512];
__device__ float g_pre[(long)BT*2048];
__device__ float g_hA[2*BB*HH];
__device__ float g_hB[2*BB*HH];
__device__ unsigned g_flags[LSTM_BLOCKS];   // one per block; dir0: 0..63, dir1: 64..127
__device__ float g_emit[(long)BT*GG];
__device__ float g_losspart[BB];

// ---------------- small builder kernels ----------------
__global__ void transpose_convw(const float* __restrict__ cw) {
    int i = blockIdx.x * blockDim.x + threadIdx.x;
    if (i < HCC * 384) {
        int o = i / 384;
        int rem = i - o * 384;
        int k = rem / DCC;
        int ii = rem - k * DCC;
        g_cwt[i] = cw[(o * DCC + ii) * 3 + k];
    }
}

__global__ void build_cwin(const int* __restrict__ bc, const float* __restrict__ cemb) {
    int bt = blockIdx.x;
    int b = bt >> 8, t = bt & 255;
    int tid = threadIdx.x;
    #pragma unroll
    for (int k = 0; k < 3; k++) {
        int ts = t + k - 1;
        float v = 0.f;
        if (ts >= 0 && ts < TT) v = cemb[(long)bc[b * TT + ts] * DCC + tid];
        g_cwin[(long)bt * 384 + k * DCC + tid] = v;
    }
}

__global__ void build_tails(const int* __restrict__ bw, const int* __restrict__ bi,
                            const int* __restrict__ blx,
                            const float* __restrict__ wemb, const float* __restrict__ lemb,
                            const float* __restrict__ iemb) {
    int bt = blockIdx.x;
    int b = bt >> 8;
    int tid = threadIdx.x;
    float iv = iemb[(long)bi[b] * 128 + tid];
    g_q [(long)bt * 512 + 384 + tid] = iv;
    g_kv[(long)bt * 512 + 384 + tid] = iv;
    int w = bw[bt];
    g_kv[(long)bt * 512 + tid]       = wemb[(long)w * 256 + tid];
    g_kv[(long)bt * 512 + 128 + tid] = wemb[(long)w * 256 + 128 + tid];
    g_kv[(long)bt * 512 + 256 + tid] = lemb[(long)blx[bt] * 128 + tid];
}

__global__ void lstm_init() {
    int i = blockIdx.x * 256 + threadIdx.x;
    if (i < LSTM_BLOCKS) g_flags[i] = 0u;
    if (i < 2 * BB * HH) g_hA[i] = 0.f;
}

// ---------------- shared f32x2 GEMM micro-kernel (16-k slab) ----------------
__device__ __forceinline__ void mac16_f32x2(
    const float (*As)[128], const float (*Bs)[128],
    int ty, int tx, unsigned long long acc[8][4])
{
    #pragma unroll
    for (int k = 0; k < 16; k++) {
        float4 a0 = *(const float4*)&As[k][ty * 4];
        float4 a1 = *(const float4*)&As[k][64 + ty * 4];
        ulonglong2 b0 = *(const ulonglong2*)&Bs[k][tx * 4];
        ulonglong2 b1 = *(const ulonglong2*)&Bs[k][64 + tx * 4];
        float av[8] = {a0.x, a0.y, a0.z, a0.w, a1.x, a1.y, a1.z, a1.w};
        unsigned long long bp[4] = {b0.x, b0.y, b1.x, b1.y};
        #pragma unroll
        for (int i = 0; i < 8; i++) {
            unsigned long long pa = dup2(av[i]);
            #pragma unroll
            for (int j = 0; j < 4; j++) ffma2(acc[i][j], pa, bp[j]);
        }
    }
}

// =====================================================================
// 128x128x16 double-buffered SGEMM (f32x2), 256 threads, 8x8 micro-tile
// =====================================================================
__global__ void __launch_bounds__(256) gemm128_nt(
    const float* __restrict__ A, const float* __restrict__ Bw, float* __restrict__ C,
    int M, int N, int K, long sA, long sB, long sC, int ldc, float scale,
    const float* __restrict__ bias1, const float* __restrict__ bias2)
{
    int bz = blockIdx.z;
    A  += (long)bz * sA;
    Bw += (long)bz * sB;
    C  += (long)bz * sC;
    int m0 = blockIdx.y * 128;
    int n0 = blockIdx.x * 128;
    __shared__ float As[2][16][128];
    __shared__ float Bs[2][16][128];
    int t = threadIdx.x;
    int tx = t & 15, ty = t >> 4;
    int lr = t >> 2, lc = t & 3;

    const float* aP = A  + (long)(m0 + lr) * K + lc * 4;
    const float* bP = Bw + (long)(n0 + lr) * K + lc * 4;
    long step64a = (long)64 * K;

    float4 ra0, ra1, rb0, rb1;
    ra0 = *(const float4*)(aP);
    ra1 = *(const float4*)(aP + step64a);
    rb0 = *(const float4*)(bP);
    rb1 = *(const float4*)(bP + step64a);

    unsigned long long acc[8][4];
    #pragma unroll
    for (int i = 0; i < 8; i++)
        #pragma unroll
        for (int j = 0; j < 4; j++) acc[i][j] = 0ull;

    int buf = 0;
    As[buf][lc*4+0][lr] = ra0.x; As[buf][lc*4+1][lr] = ra0.y;
    As[buf][lc*4+2][lr] = ra0.z; As[buf][lc*4+3][lr] = ra0.w;
    As[buf][lc*4+0][lr+64] = ra1.x; As[buf][lc*4+1][lr+64] = ra1.y;
    As[buf][lc*4+2][lr+64] = ra1.z; As[buf][lc*4+3][lr+64] = ra1.w;
    Bs[buf][lc*4+0][lr] = rb0.x; Bs[buf][lc*4+1][lr] = rb0.y;
    Bs[buf][lc*4+2][lr] = rb0.z; Bs[buf][lc*4+3][lr] = rb0.w;
    Bs[buf][lc*4+0][lr+64] = rb1.x; Bs[buf][lc*4+1][lr+64] = rb1.y;
    Bs[buf][lc*4+2][lr+64] = rb1.z; Bs[buf][lc*4+3][lr+64] = rb1.w;
    __syncthreads();

    int nIter = K / 16;
    for (int it = 1; it < nIter; it++) {
        int k0 = it * 16;
        ra0 = *(const float4*)(aP + k0);
        ra1 = *(const float4*)(aP + step64a + k0);
        rb0 = *(const float4*)(bP + k0);
        rb1 = *(const float4*)(bP + step64a + k0);
        mac16_f32x2(As[buf], Bs[buf], ty, tx, acc);
        int nb = buf ^ 1;
        As[nb][lc*4+0][lr] = ra0.x; As[nb][lc*4+1][lr] = ra0.y;
        As[nb][lc*4+2][lr] = ra0.z; As[nb][lc*4+3][lr] = ra0.w;
        As[nb][lc*4+0][lr+64] = ra1.x; As[nb][lc*4+1][lr+64] = ra1.y;
        As[nb][lc*4+2][lr+64] = ra1.z; As[nb][lc*4+3][lr+64] = ra1.w;
        Bs[nb][lc*4+0][lr] = rb0.x; Bs[nb][lc*4+1][lr] = rb0.y;
        Bs[nb][lc*4+2][lr] = rb0.z; Bs[nb][lc*4+3][lr] = rb0.w;
        Bs[nb][lc*4+0][lr+64] = rb1.x; Bs[nb][lc*4+1][lr+64] = rb1.y;
        Bs[nb][lc*4+2][lr+64] = rb1.z; Bs[nb][lc*4+3][lr+64] = rb1.w;
        __syncthreads();
        buf = nb;
    }
    mac16_f32x2(As[buf], Bs[buf], ty, tx, acc);

    #pragma unroll
    for (int mh = 0; mh < 2; mh++)
        #pragma unroll
        for (int i = 0; i < 4; i++) {
            int m = m0 + mh * 64 + ty * 4 + i;
            int r = mh * 4 + i;
            #pragma unroll
            for (int nh = 0; nh < 2; nh++) {
                int n = n0 + nh * 64 + tx * 4;
                float4 v;
                unpk2(acc[r][nh*2+0], v.x, v.y);
                unpk2(acc[r][nh*2+1], v.z, v.w);
                v.x *= scale; v.y *= scale; v.z *= scale; v.w *= scale;
                if (bias1) { v.x += bias1[n]; v.y += bias1[n+1]; v.z += bias1[n+2]; v.w += bias1[n+3]; }
                if (bias2) { v.x += bias2[n]; v.y += bias2[n+1]; v.z += bias2[n+2]; v.w += bias2[n+3]; }
                *(float4*)(C + (long)m * ldc + n) = v;
            }
        }
}

// C[bz](MxN) = A(MxK) @ B(KxN row-major, ldb)   (f32x2)
__global__ void __launch_bounds__(256) gemm128_nn(
    const float* __restrict__ A, const float* __restrict__ Bm, float* __restrict__ C,
    int M, int N, int K, int ldb, int ldc, long sA, long sB, long sC)
{
    int bz = blockIdx.z;
    A  += (long)bz * sA;
    Bm += (long)bz * sB;
    C  += (long)bz * sC;
    int m0 = blockIdx.y * 128;
    int n0 = blockIdx.x * 128;
    __shared__ float As[2][16][128];
    __shared__ float Bs[2][16][128];
    int t = threadIdx.x;
    int tx = t & 15, ty = t >> 4;
    int lr = t >> 2, lc = t & 3;
    int kr = t >> 4, nc = t & 15;

    const float* aP = A + (long)(m0 + lr) * K + lc * 4;
    long step64a = (long)64 * K;
    const float* bP = Bm + (long)kr * ldb + n0 + nc * 4;

    float4 ra0, ra1, rb0, rb1;
    ra0 = *(const float4*)(aP);
    ra1 = *(const float4*)(aP + step64a);
    rb0 = *(const float4*)(bP);
    rb1 = *(const float4*)(bP + 64);

    unsigned long long acc[8][4];
    #pragma unroll
    for (int i = 0; i < 8; i++)
        #pragma unroll
        for (int j = 0; j < 4; j++) acc[i][j] = 0ull;

    int buf = 0;
    As[buf][lc*4+0][lr] = ra0.x; As[buf][lc*4+1][lr] = ra0.y;
    As[buf][lc*4+2][lr] = ra0.z; As[buf][lc*4+3][lr] = ra0.w;
    As[buf][lc*4+0][lr+64] = ra1.x; As[buf][lc*4+1][lr+64] = ra1.y;
    As[buf][lc*4+2][lr+64] = ra1.z; As[buf][lc*4+3][lr+64] = ra1.w;
    *(float4*)&Bs[buf][kr][nc * 4] = rb0;
    *(float4*)&Bs[buf][kr][64 + nc * 4] = rb1;
    __syncthreads();

    int nIter = K / 16;
    for (int it = 1; it < nIter; it++) {
        int k0 = it * 16;
        ra0 = *(const float4*)(aP + k0);
        ra1 = *(const float4*)(aP + step64a + k0);
        rb0 = *(const float4*)(bP + (long)k0 * ldb);
        rb1 = *(const float4*)(bP + (long)k0 * ldb + 64);
        mac16_f32x2(As[buf], Bs[buf], ty, tx, acc);
        int nb = buf ^ 1;
        As[nb][lc*4+0][lr] = ra0.x; As[nb][lc*4+1][lr] = ra0.y;
        As[nb][lc*4+2][lr] = ra0.z; As[nb][lc*4+3][lr] = ra0.w;
        As[nb][lc*4+0][lr+64] = ra1.x; As[nb][lc*4+1][lr+64] = ra1.y;
        As[nb][lc*4+2][lr+64] = ra1.z; As[nb][lc*4+3][lr+64] = ra1.w;
        *(float4*)&Bs[nb][kr][nc * 4] = rb0;
        *(float4*)&Bs[nb][kr][64 + nc * 4] = rb1;
        __syncthreads();
        buf = nb;
    }
    mac16_f32x2(As[buf], Bs[buf], ty, tx, acc);

    #pragma unroll
    for (int mh = 0; mh < 2; mh++)
        #pragma unroll
        for (int i = 0; i < 4; i++) {
            int m = m0 + mh * 64 + ty * 4 + i;
            int r = mh * 4 + i;
            #pragma unroll
            for (int nh = 0; nh < 2; nh++) {
                int n = n0 + nh * 64 + tx * 4;
                float4 v;
                unpk2(acc[r][nh*2+0], v.x, v.y);
                unpk2(acc[r][nh*2+1], v.z, v.w);
                *(float4*)(C + (long)m * ldc + n) = v;
            }
        }
}

// ---------------- small-N GEMM (emissions, N=66) ----------------
__global__ void gemm_nt(const float* __restrict__ A, const float* __restrict__ Bw,
                        float* __restrict__ C,
                        int M, int N, int K,
                        long sA, long sB, long sC, int ldc,
                        float scale,
                        const float* __restrict__ bias1, const float* __restrict__ bias2) {
    int bz = blockIdx.z;
    A  += (long)bz * sA;
    Bw += (long)bz * sB;
    C  += (long)bz * sC;
    int m0 = blockIdx.y * 64;
    int n0 = blockIdx.x * 64;
    __shared__ float As[16][68];
    __shared__ float Bs[16][68];
    int t = threadIdx.x;
    int tx = t & 15, ty = t >> 4;
    float acc[4][4];
    #pragma unroll
    for (int i = 0; i < 4; i++)
        #pragma unroll
        for (int j = 0; j < 4; j++) acc[i][j] = 0.f;
    int r = t >> 2;
    int cq = t & 3;
    for (int k0 = 0; k0 < K; k0 += 16) {
        float4 av = *(const float4*)(A + (long)(m0 + r) * K + k0 + cq * 4);
        As[cq * 4 + 0][r] = av.x; As[cq * 4 + 1][r] = av.y;
        As[cq * 4 + 2][r] = av.z; As[cq * 4 + 3][r] = av.w;
        float4 bv = make_float4(0.f, 0.f, 0.f, 0.f);
        if (n0 + r < N) bv = *(const float4*)(Bw + (long)(n0 + r) * K + k0 + cq * 4);
        Bs[cq * 4 + 0][r] = bv.x; Bs[cq * 4 + 1][r] = bv.y;
        Bs[cq * 4 + 2][r] = bv.z; Bs[cq * 4 + 3][r] = bv.w;
        __syncthreads();
        #pragma unroll
        for (int kk = 0; kk < 16; kk++) {
            float4 a  = *(const float4*)&As[kk][ty * 4];
            float4 bb = *(const float4*)&Bs[kk][tx * 4];
            acc[0][0] += a.x * bb.x; acc[0][1] += a.x * bb.y; acc[0][2] += a.x * bb.z; acc[0][3] += a.x * bb.w;
            acc[1][0] += a.y * bb.x; acc[1][1] += a.y * bb.y; acc[1][2] += a.y * bb.z; acc[1][3] += a.y * bb.w;
            acc[2][0] += a.z * bb.x; acc[2][1] += a.z * bb.y; acc[2][2] += a.z * bb.z; acc[2][3] += a.z * bb.w;
            acc[3][0] += a.w * bb.x; acc[3][1] += a.w * bb.y; acc[3][2] += a.w * bb.z; acc[3][3] += a.w * bb.w;
        }
        __syncthreads();
    }
    #pragma unroll
    for (int i = 0; i < 4; i++) {
        int m = m0 + ty * 4 + i;
        #pragma unroll
        for (int j = 0; j < 4; j++) {
            int n = n0 + tx * 4 + j;
            if (n < N) {
                float v = acc[i][j] * scale;
                if (bias1) v += bias1[n];
                if (bias2) v += bias2[n];
                C[(long)m * ldc + n] = v;
            }
        }
    }
}

// ---------------- softmax over rows of 256 ----------------
__global__ void softmax_rows(float* __restrict__ sc) {
    int row = blockIdx.x;
    int t = threadIdx.x;
    __shared__ float red[256];
    float v = sc[(long)row * 256 + t];
    red[t] = v;
    __syncthreads();
    for (int s = 128; s > 0; s >>= 1) {
        if (t < s) red[t] = fmaxf(red[t], red[t + s]);
        __syncthreads();
    }
    float m = red[0];
    __syncthreads();
    float e = expf(v - m);
    red[t] = e;
    __syncthreads();
    for (int s = 128; s > 0; s >>= 1) {
        if (t < s) red[t] += red[t + s];
        __syncthreads();
    }
    float inv = 1.f / red[0];
    sc[(long)row * 256 + t] = e * inv;
}

// =====================================================================
// Persistent BiLSTM layer: R15 body + FLAT flag barrier.
// Arrival: each block release-stores its own flag (parallel, no RMW
// serialization). Wait: lanes 0..63 each poll one flag of this direction
// directly (no master indirection), then block-sync.
// =====================================================================
__global__ void __launch_bounds__(256) lstm_layer2(
    const float* __restrict__ pre,   // [BT][2048]  dir*1024 + g*256 + u
    const float* __restrict__ whh,   // [2][1024][256]
    float* __restrict__ out)         // [BT][512]   dir*256 + u
{
    extern __shared__ float sm[];
    float* ws    = sm;                    // 4096 floats
    float* pre_s = sm + 4096;             // 1024 floats
    float4* hs4  = (float4*)(sm + 5120);  // 4160 float4: k4*65 + b

    int blk = blockIdx.x;
    int dir = blk >> 6;
    int u0 = (blk & 63) * 4;
    int tid = threadIdx.x;
    int uu = tid >> 6;
    int b = tid & 63;
    int u = u0 + uu;
    int dirbase = dir * 64;

    const float* wbase = whh + (long)dir * 1024 * 256;
    for (int i = tid; i < 4096; i += 256) {
        int uui = i >> 10;
        int g = (i >> 8) & 3;
        int k = i & 255;
        ws[i] = wbase[(long)(g * 256 + u0 + uui) * 256 + k];
    }

    float* hAd = g_hA + dir * BB * HH;
    float* hBd = g_hB + dir * BB * HH;

    const ulonglong2* hsu = (const ulonglong2*)hs4;
    const ulonglong2* wu2 = (const ulonglong2*)ws + uu * 256;

    int sb = tid >> 2, sg = tid & 3;
    const float* preB = pre + (long)sb * TT * 2048 + dir * 1024 + sg * 256 + u0;
    float c = 0.f;

    // prefetch pre for step 0
    int ts0 = dir ? (TT - 1) : 0;
    float4 preg = __ldcg((const float4*)(preB + (long)ts0 * 2048));

    for (int s = 0; s < TT; s++) {
        int tstep = dir ? (TT - 1 - s) : s;
        const float4* hin4 = (const float4*)((s & 1) ? hBd : hAd);
        float* hout = (s & 1) ? hAd : hBd;

        // stage pre slice from prefetched register
        pre_s[(sg * 4 + 0) * 64 + sb] = preg.x;
        pre_s[(sg * 4 + 1) * 64 + sb] = preg.y;
        pre_s[(sg * 4 + 2) * 64 + sb] = preg.z;
        pre_s[(sg * 4 + 3) * 64 + sb] = preg.w;
        // stage h[64][256] transposed into smem
        #pragma unroll
        for (int j = 0; j < 16; j++) {
            int idx = tid + j * 256;
            int hb = idx >> 6, k4 = idx & 63;
            float4 v = __ldcg(hin4 + hb * 64 + k4);
            hs4[k4 * 65 + hb] = v;
        }
        __syncthreads();

        // prefetch next step's pre (clamped; deterministic)
        {
            int snx = (s + 1 < TT) ? (s + 1) : s;
            int tnx = dir ? (TT - 1 - snx) : snx;
            preg = __ldcg((const float4*)(preB + (long)tnx * 2048));
        }

        float p0 = pre_s[(0 * 4 + uu) * 64 + b];
        float p1 = pre_s[(1 * 4 + uu) * 64 + b];
        float p2 = pre_s[(2 * 4 + uu) * 64 + b];
        float p3 = pre_s[(3 * 4 + uu) * 64 + b];

        unsigned long long ac0 = 0ull, ac1 = 0ull, ac2 = 0ull, ac3 = 0ull;
        #pragma unroll 8
        for (int k4 = 0; k4 < 64; k4++) {
            ulonglong2 hv = hsu[k4 * 65 + b];
            ulonglong2 w0 = wu2[k4];
            ulonglong2 w1 = wu2[64 + k4];
            ulonglong2 w2 = wu2[128 + k4];
            ulonglong2 w3 = wu2[192 + k4];
            ffma2(ac0, w0.x, hv.x); ffma2(ac0, w0.y, hv.y);
            ffma2(ac1, w1.x, hv.x); ffma2(ac1, w1.y, hv.y);
            ffma2(ac2, w2.x, hv.x); ffma2(ac2, w2.y, hv.y);
            ffma2(ac3, w3.x, hv.x); ffma2(ac3, w3.y, hv.y);
        }
        float lo, hi;
        unpk2(ac0, lo, hi); float a0 = p0 + lo + hi;
        unpk2(ac1, lo, hi); float a1 = p1 + lo + hi;
        unpk2(ac2, lo, hi); float a2 = p2 + lo + hi;
        unpk2(ac3, lo, hi); float a3 = p3 + lo + hi;

        float iv = 1.f / (1.f + expf(-a0));
        float fv = 1.f / (1.f + expf(-a1));
        float gv = tanhf(a2);
        float ov = 1.f / (1.f + expf(-a3));
        c = fv * c + iv * gv;
        float h = ov * tanhf(c);

        hout[b * HH + u] = h;

        if (s + 1 < TT) {
            __threadfence();        // h globally visible before flag publish
            __syncthreads();        // all threads' h written + fenced

            if (tid == 0) st_rel(&g_flags[blk], (unsigned)(s + 1));

            // overlap sequence-output store with the barrier wait
            out[((long)(b * TT + tstep)) * 512 + dir * 256 + u] = h;

            // flat wait: lanes 0..63 each poll one flag of this direction
            if (tid < 64) {
                unsigned target = (unsigned)(s + 1);
                while (ld_acq(&g_flags[dirbase + tid]) < target) { }
            }
            __syncthreads();
        } else {
            out[((long)(b * TT + tstep)) * 512 + dir * 256 + u] = h;
        }
    }
}

// ---------------- CRF NLL forward (one block per batch) ----------------
__global__ void crf_nll_kernel(const float* __restrict__ emit, const float* __restrict__ trans,
                               const int* __restrict__ tags) {
    int b = blockIdx.x;
    int t = threadIdx.x;
    __shared__ float tr[GG * GG];
    __shared__ float alpha[GG];
    for (int i = t; i < GG * GG; i += 128) tr[i] = trans[i];
    __syncthreads();
    if (t < GG) alpha[t] = tr[ST_START * GG + t] + emit[((long)b * TT) * GG + t];
    __syncthreads();
    for (int step = 1; step < TT; step++) {
        float anew = 0.f;
        if (t < GG) {
            float m = -1e30f;
            for (int i = 0; i < GG; i++) m = fmaxf(m, alpha[i] + tr[i * GG + t]);
            float sum = 0.f;
            for (int i = 0; i < GG; i++) sum += expf(alpha[i] + tr[i * GG + t] - m);
            anew = m + logf(sum) + emit[((long)b * TT + step) * GG + t];
        }
        __syncthreads();
        if (t < GG) alpha[t] = anew;
        __syncthreads();
    }
    if (t == 0) {
        float m = -1e30f;
        for (int j = 0; j < GG; j++) m = fmaxf(m, alpha[j] + tr[j * GG + ST_STOP]);
        float s = 0.f;
        for (int j = 0; j < GG; j++) s += expf(alpha[j] + tr[j * GG + ST_STOP] - m);
        float logZ = m + logf(s);
        const int* tg = tags + b * TT;
        float gold = tr[ST_START * GG + tg[0]];
        for (int k = 0; k < TT; k++) gold += emit[((long)b * TT + k) * GG + tg[k]];
        for (int k = 0; k < TT - 1; k++) gold += tr[tg[k] * GG + tg[k + 1]];
        gold += tr[tg[TT - 1] * GG + ST_STOP];
        g_losspart[b] = logZ - gold;
    }
}

__global__ void reduce_loss(float* __restrict__ out) {
    if (threadIdx.x == 0) {
        float s = 0.f;
        for (int b = 0; b < BB; b++) s += g_losspart[b];
        out[0] = s;
    }
}

// ---------------- Viterbi ----------------
__global__ void viterbi_kernel(const float* __restrict__ emit, const float* __restrict__ trans,
                               float* __restrict__ out) {
    int b = blockIdx.x;
    int t = threadIdx.x;
    __shared__ float tr[GG * GG];
    __shared__ float delta[GG];
    __shared__ unsigned char bp[TT][GG];
    for (int i = t; i < GG * GG; i += 128) tr[i] = trans[i];
    __syncthreads();
    if (t < GG) delta[t] = tr[ST_START * GG + t] + emit[((long)b * TT) * GG + t];
    __syncthreads();
    for (int step = 1; step < TT; step++) {
        float best = -1e30f;
        int arg = 0;
        if (t < GG) {
            for (int i = 0; i < GG; i++) {
                float v = delta[i] + tr[i * GG + t];
                if (v > best) { best = v; arg = i; }
            }
            best += emit[((long)b * TT + step) * GG + t];
        }
        __syncthreads();
        if (t < GG) { delta[t] = best; bp[step][t] = (unsigned char)arg; }
        __syncthreads();
    }
    if (t == 0) {
        float best = -1e30f;
        int tag = 0;
        for (int j = 0; j < GG; j++) {
            float v = delta[j] + tr[j * GG + ST_STOP];
            if (v > best) { best = v; tag = j; }
        }
        out[1 + b * TT + (TT - 1)] = (float)tag;
        for (int step = TT - 1; step >= 1; step--) {
            tag = bp[step][tag];
            out[1 + b * TT + step - 1] = (float)tag;
        }
    }
}

// ---------------- host driver ----------------
extern "C" void kernel_launch(void* const* d_in, const int* in_sizes, int n_in,
                              void* d_out, int out_size) {
    const int*   bw    = (const int*)d_in[0];
    const int*   bi    = (const int*)d_in[1];
    const int*   bc    = (const int*)d_in[3];
    const int*   blx   = (const int*)d_in[6];
    const int*   blab  = (const int*)d_in[7];
    const float* cemb  = (const float*)d_in[8];
    const float* wemb  = (const float*)d_in[9];
    const float* lemb  = (const float*)d_in[10];
    const float* iemb  = (const float*)d_in[11];
    const float* convw = (const float*)d_in[12];
    const float* convb = (const float*)d_in[13];
    const float* wih   = (const float*)d_in[14];
    const float* whh   = (const float*)d_in[15];
    const float* bih   = (const float*)d_in[16];
    const float* bhh   = (const float*)d_in[17];
    const float* pw    = (const float*)d_in[18];
    const float* pb    = (const float*)d_in[19];
    const float* trans = (const float*)d_in[20];
    float* out = (float*)d_out;

    float *p_cwin, *p_cwt, *p_q, *p_kv, *p_sc, *p_x0, *p_x1, *p_x2, *p_pre, *p_emit;
    cudaGetSymbolAddress((void**)&p_cwin, g_cwin);
    cudaGetSymbolAddress((void**)&p_cwt,  g_cwt);
    cudaGetSymbolAddress((void**)&p_q,    g_q);
    cudaGetSymbolAddress((void**)&p_kv,   g_kv);
    cudaGetSymbolAddress((void**)&p_sc,   g_sc);
    cudaGetSymbolAddress((void**)&p_x0,   g_x0);
    cudaGetSymbolAddress((void**)&p_x1,   g_x1);
    cudaGetSymbolAddress((void**)&p_x2,   g_x2);
    cudaGetSymbolAddress((void**)&p_pre,  g_pre);
    cudaGetSymbolAddress((void**)&p_emit, g_emit);

    const int lstm_smem = (4096 + 1024 + 4160 * 4) * 4;  // 87040 B
    cudaFuncSetAttribute(lstm_layer2, cudaFuncAttributeMaxDynamicSharedMemorySize, lstm_smem);

    const float inv_temp = 1.0f / sqrtf(128.0f);

    // 1) inputs assembly
    transpose_convw<<<(HCC * 384 + 255) / 256, 256>>>(convw);
    build_cwin<<<BT, 128>>>(bc, cemb);
    build_tails<<<BT, 128>>>(bw, bi, blx, wemb, lemb, iemb);

    // 2) char CNN as GEMM
    gemm128_nt<<<dim3(3, 128, 1), 256>>>(p_cwin, p_cwt, p_q,
                                         BT, 384, 384, 0, 0, 0, 512,
                                         1.0f, convb, nullptr);

    // 3) attention scores
    gemm128_nt<<<dim3(2, 2, BB), 256>>>(p_q, p_kv, p_sc,
                                        256, 256, 512,
                                        (long)TT * 512, (long)TT * 512, (long)TT * 256, 256,
                                        inv_temp, nullptr, nullptr);
    softmax_rows<<<BT, 256>>>(p_sc);

    // 4) context
    gemm128_nn<<<dim3(4, 2, BB), 256>>>(p_sc, p_kv, p_x0,
                                        256, 512, 256, 512, 512,
                                        (long)TT * 256, (long)TT * 512, (long)TT * 512);

    // 5) two BiLSTM layers
    for (int l = 0; l < 2; l++) {
        const float* xin  = (l == 0) ? p_x0 : p_x1;
        float*       xout = (l == 0) ? p_x1 : p_x2;
        gemm128_nt<<<dim3(16, 128, 1), 256>>>(xin, wih + (long)l * 2 * H44 * LHH, p_pre,
                                              BT, 2048, 512, 0, 0, 0, 2048,
                                              1.0f, bih + l * 2 * H44, bhh + l * 2 * H44);
        lstm_init<<<128, 256>>>();
        lstm_layer2<<<LSTM_BLOCKS, 256, lstm_smem>>>(p_pre, whh + (long)l * 2 * H44 * HH, xout);
    }

    // 6) emissions
    gemm_nt<<<dim3(2, 256, 1), 256>>>(p_x2, pw, p_emit,
                                      BT, GG, 512, 0, 0, 0, GG,
                                      1.0f, pb, nullptr);

    // 7) CRF NLL + Viterbi
    crf_nll_kernel<<<BB, 128>>>(p_emit, trans, blab);
    reduce_loss<<<1, 32>>>(out);
    viterbi_kernel<<<BB, 128>>>(p_emit, trans, out);
}

// round 17
// speedup vs baseline: 1.6994x; 1.6994x over previous
#include <cuda_runtime.h>
#include <math.h>

// ---------------- problem constants ----------------
#define BB 64
#define TT 256
#define GG 66
#define DCC 128
#define HCC 384
#define LHH 512
#define HH 256
#define H44 1024
#define ST_START 64
#define ST_STOP 65
#define BT (BB*TT)
#define LSTM_BLOCKS 128

// ---------------- packed fp32x2 helpers (sm_100+) ----------------
__device__ __forceinline__ void ffma2(unsigned long long& acc,
                                      unsigned long long a, unsigned long long b) {
    asm("fma.rn.f32x2 %0, %1, %2, %0;" : "+l"(acc) : "l"(a), "l"(b));
}
__device__ __forceinline__ unsigned long long dup2(float x) {
    unsigned long long r;
    asm("mov.b64 %0, {%1, %1};" : "=l"(r) : "f"(x));
    return r;
}
__device__ __forceinline__ void unpk2(unsigned long long v, float& lo, float& hi) {
    asm("mov.b64 {%0, %1}, %2;" : "=f"(lo), "=f"(hi) : "l"(v));
}

// ---------------- scratch (__device__ globals; no allocation allowed) -------
__device__ float g_cwin[(long)BT*384];
__device__ float g_cwt[HCC*384];
__device__ float g_q[(long)BT*512];
__device__ float g_kv[(long)BT*512];
__device__ float g_sc[(long)BT*256];
__device__ float g_x0[(long)BT*512];
__device__ float g_x1[(long)BT*512];
__device__ float g_x2[(long)BT*512];
__device__ float g_pre[(long)BT*2048];
__device__ float g_hA[2*BB*HH];
__device__ float g_hB[2*BB*HH];
// 8 arrival counters per direction, each on its own 128B line
__device__ unsigned g_barM[2*8*32];
__device__ float g_emit[(long)BT*GG];
__device__ float g_losspart[BB];

// ---------------- small builder kernels ----------------
__global__ void transpose_convw(const float* __restrict__ cw) {
    int i = blockIdx.x * blockDim.x + threadIdx.x;
    if (i < HCC * 384) {
        int o = i / 384;
        int rem = i - o * 384;
        int k = rem / DCC;
        int ii = rem - k * DCC;
        g_cwt[i] = cw[(o * DCC + ii) * 3 + k];
    }
}

__global__ void build_cwin(const int* __restrict__ bc, const float* __restrict__ cemb) {
    int bt = blockIdx.x;
    int b = bt >> 8, t = bt & 255;
    int tid = threadIdx.x;
    #pragma unroll
    for (int k = 0; k < 3; k++) {
        int ts = t + k - 1;
        float v = 0.f;
        if (ts >= 0 && ts < TT) v = cemb[(long)bc[b * TT + ts] * DCC + tid];
        g_cwin[(long)bt * 384 + k * DCC + tid] = v;
    }
}

__global__ void build_tails(const int* __restrict__ bw, const int* __restrict__ bi,
                            const int* __restrict__ blx,
                            const float* __restrict__ wemb, const float* __restrict__ lemb,
                            const float* __restrict__ iemb) {
    int bt = blockIdx.x;
    int b = bt >> 8;
    int tid = threadIdx.x;
    float iv = iemb[(long)bi[b] * 128 + tid];
    g_q [(long)bt * 512 + 384 + tid] = iv;
    g_kv[(long)bt * 512 + 384 + tid] = iv;
    int w = bw[bt];
    g_kv[(long)bt * 512 + tid]       = wemb[(long)w * 256 + tid];
    g_kv[(long)bt * 512 + 128 + tid] = wemb[(long)w * 256 + 128 + tid];
    g_kv[(long)bt * 512 + 256 + tid] = lemb[(long)blx[bt] * 128 + tid];
}

__global__ void lstm_init() {
    int i = blockIdx.x * 256 + threadIdx.x;
    if (i < 2 * 8 * 32) g_barM[i] = 0u;
    if (i < 2 * BB * HH) g_hA[i] = 0.f;
}

// ---------------- shared f32x2 GEMM micro-kernel (16-k slab) ----------------
__device__ __forceinline__ void mac16_f32x2(
    const float (*As)[128], const float (*Bs)[128],
    int ty, int tx, unsigned long long acc[8][4])
{
    #pragma unroll
    for (int k = 0; k < 16; k++) {
        float4 a0 = *(const float4*)&As[k][ty * 4];
        float4 a1 = *(const float4*)&As[k][64 + ty * 4];
        ulonglong2 b0 = *(const ulonglong2*)&Bs[k][tx * 4];
        ulonglong2 b1 = *(const ulonglong2*)&Bs[k][64 + tx * 4];
        float av[8] = {a0.x, a0.y, a0.z, a0.w, a1.x, a1.y, a1.z, a1.w};
        unsigned long long bp[4] = {b0.x, b0.y, b1.x, b1.y};
        #pragma unroll
        for (int i = 0; i < 8; i++) {
            unsigned long long pa = dup2(av[i]);
            #pragma unroll
            for (int j = 0; j < 4; j++) ffma2(acc[i][j], pa, bp[j]);
        }
    }
}

// =====================================================================
// 128x128x16 double-buffered SGEMM (f32x2), 256 threads, 8x8 micro-tile
// =====================================================================
__global__ void __launch_bounds__(256) gemm128_nt(
    const float* __restrict__ A, const float* __restrict__ Bw, float* __restrict__ C,
    int M, int N, int K, long sA, long sB, long sC, int ldc, float scale,
    const float* __restrict__ bias1, const float* __restrict__ bias2)
{
    int bz = blockIdx.z;
    A  += (long)bz * sA;
    Bw += (long)bz * sB;
    C  += (long)bz * sC;
    int m0 = blockIdx.y * 128;
    int n0 = blockIdx.x * 128;
    __shared__ float As[2][16][128];
    __shared__ float Bs[2][16][128];
    int t = threadIdx.x;
    int tx = t & 15, ty = t >> 4;
    int lr = t >> 2, lc = t & 3;

    const float* aP = A  + (long)(m0 + lr) * K + lc * 4;
    const float* bP = Bw + (long)(n0 + lr) * K + lc * 4;
    long step64a = (long)64 * K;

    float4 ra0, ra1, rb0, rb1;
    ra0 = *(const float4*)(aP);
    ra1 = *(const float4*)(aP + step64a);
    rb0 = *(const float4*)(bP);
    rb1 = *(const float4*)(bP + step64a);

    unsigned long long acc[8][4];
    #pragma unroll
    for (int i = 0; i < 8; i++)
        #pragma unroll
        for (int j = 0; j < 4; j++) acc[i][j] = 0ull;

    int buf = 0;
    As[buf][lc*4+0][lr] = ra0.x; As[buf][lc*4+1][lr] = ra0.y;
    As[buf][lc*4+2][lr] = ra0.z; As[buf][lc*4+3][lr] = ra0.w;
    As[buf][lc*4+0][lr+64] = ra1.x; As[buf][lc*4+1][lr+64] = ra1.y;
    As[buf][lc*4+2][lr+64] = ra1.z; As[buf][lc*4+3][lr+64] = ra1.w;
    Bs[buf][lc*4+0][lr] = rb0.x; Bs[buf][lc*4+1][lr] = rb0.y;
    Bs[buf][lc*4+2][lr] = rb0.z; Bs[buf][lc*4+3][lr] = rb0.w;
    Bs[buf][lc*4+0][lr+64] = rb1.x; Bs[buf][lc*4+1][lr+64] = rb1.y;
    Bs[buf][lc*4+2][lr+64] = rb1.z; Bs[buf][lc*4+3][lr+64] = rb1.w;
    __syncthreads();

    int nIter = K / 16;
    for (int it = 1; it < nIter; it++) {
        int k0 = it * 16;
        ra0 = *(const float4*)(aP + k0);
        ra1 = *(const float4*)(aP + step64a + k0);
        rb0 = *(const float4*)(bP + k0);
        rb1 = *(const float4*)(bP + step64a + k0);
        mac16_f32x2(As[buf], Bs[buf], ty, tx, acc);
        int nb = buf ^ 1;
        As[nb][lc*4+0][lr] = ra0.x; As[nb][lc*4+1][lr] = ra0.y;
        As[nb][lc*4+2][lr] = ra0.z; As[nb][lc*4+3][lr] = ra0.w;
        As[nb][lc*4+0][lr+64] = ra1.x; As[nb][lc*4+1][lr+64] = ra1.y;
        As[nb][lc*4+2][lr+64] = ra1.z; As[nb][lc*4+3][lr+64] = ra1.w;
        Bs[nb][lc*4+0][lr] = rb0.x; Bs[nb][lc*4+1][lr] = rb0.y;
        Bs[nb][lc*4+2][lr] = rb0.z; Bs[nb][lc*4+3][lr] = rb0.w;
        Bs[nb][lc*4+0][lr+64] = rb1.x; Bs[nb][lc*4+1][lr+64] = rb1.y;
        Bs[nb][lc*4+2][lr+64] = rb1.z; Bs[nb][lc*4+3][lr+64] = rb1.w;
        __syncthreads();
        buf = nb;
    }
    mac16_f32x2(As[buf], Bs[buf], ty, tx, acc);

    #pragma unroll
    for (int mh = 0; mh < 2; mh++)
        #pragma unroll
        for (int i = 0; i < 4; i++) {
            int m = m0 + mh * 64 + ty * 4 + i;
            int r = mh * 4 + i;
            #pragma unroll
            for (int nh = 0; nh < 2; nh++) {
                int n = n0 + nh * 64 + tx * 4;
                float4 v;
                unpk2(acc[r][nh*2+0], v.x, v.y);
                unpk2(acc[r][nh*2+1], v.z, v.w);
                v.x *= scale; v.y *= scale; v.z *= scale; v.w *= scale;
                if (bias1) { v.x += bias1[n]; v.y += bias1[n+1]; v.z += bias1[n+2]; v.w += bias1[n+3]; }
                if (bias2) { v.x += bias2[n]; v.y += bias2[n+1]; v.z += bias2[n+2]; v.w += bias2[n+3]; }
                *(float4*)(C + (long)m * ldc + n) = v;
            }
        }
}

// C[bz](MxN) = A(MxK) @ B(KxN row-major, ldb)   (f32x2)
__global__ void __launch_bounds__(256) gemm128_nn(
    const float* __restrict__ A, const float* __restrict__ Bm, float* __restrict__ C,
    int M, int N, int K, int ldb, int ldc, long sA, long sB, long sC)
{
    int bz = blockIdx.z;
    A  += (long)bz * sA;
    Bm += (long)bz * sB;
    C  += (long)bz * sC;
    int m0 = blockIdx.y * 128;
    int n0 = blockIdx.x * 128;
    __shared__ float As[2][16][128];
    __shared__ float Bs[2][16][128];
    int t = threadIdx.x;
    int tx = t & 15, ty = t >> 4;
    int lr = t >> 2, lc = t & 3;
    int kr = t >> 4, nc = t & 15;

    const float* aP = A + (long)(m0 + lr) * K + lc * 4;
    long step64a = (long)64 * K;
    const float* bP = Bm + (long)kr * ldb + n0 + nc * 4;

    float4 ra0, ra1, rb0, rb1;
    ra0 = *(const float4*)(aP);
    ra1 = *(const float4*)(aP + step64a);
    rb0 = *(const float4*)(bP);
    rb1 = *(const float4*)(bP + 64);

    unsigned long long acc[8][4];
    #pragma unroll
    for (int i = 0; i < 8; i++)
        #pragma unroll
        for (int j = 0; j < 4; j++) acc[i][j] = 0ull;

    int buf = 0;
    As[buf][lc*4+0][lr] = ra0.x; As[buf][lc*4+1][lr] = ra0.y;
    As[buf][lc*4+2][lr] = ra0.z; As[buf][lc*4+3][lr] = ra0.w;
    As[buf][lc*4+0][lr+64] = ra1.x; As[buf][lc*4+1][lr+64] = ra1.y;
    As[buf][lc*4+2][lr+64] = ra1.z; As[buf][lc*4+3][lr+64] = ra1.w;
    *(float4*)&Bs[buf][kr][nc * 4] = rb0;
    *(float4*)&Bs[buf][kr][64 + nc * 4] = rb1;
    __syncthreads();

    int nIter = K / 16;
    for (int it = 1; it < nIter; it++) {
        int k0 = it * 16;
        ra0 = *(const float4*)(aP + k0);
        ra1 = *(const float4*)(aP + step64a + k0);
        rb0 = *(const float4*)(bP + (long)k0 * ldb);
        rb1 = *(const float4*)(bP + (long)k0 * ldb + 64);
        mac16_f32x2(As[buf], Bs[buf], ty, tx, acc);
        int nb = buf ^ 1;
        As[nb][lc*4+0][lr] = ra0.x; As[nb][lc*4+1][lr] = ra0.y;
        As[nb][lc*4+2][lr] = ra0.z; As[nb][lc*4+3][lr] = ra0.w;
        As[nb][lc*4+0][lr+64] = ra1.x; As[nb][lc*4+1][lr+64] = ra1.y;
        As[nb][lc*4+2][lr+64] = ra1.z; As[nb][lc*4+3][lr+64] = ra1.w;
        *(float4*)&Bs[nb][kr][nc * 4] = rb0;
        *(float4*)&Bs[nb][kr][64 + nc * 4] = rb1;
        __syncthreads();
        buf = nb;
    }
    mac16_f32x2(As[buf], Bs[buf], ty, tx, acc);

    #pragma unroll
    for (int mh = 0; mh < 2; mh++)
        #pragma unroll
        for (int i = 0; i < 4; i++) {
            int m = m0 + mh * 64 + ty * 4 + i;
            int r = mh * 4 + i;
            #pragma unroll
            for (int nh = 0; nh < 2; nh++) {
                int n = n0 + nh * 64 + tx * 4;
                float4 v;
                unpk2(acc[r][nh*2+0], v.x, v.y);
                unpk2(acc[r][nh*2+1], v.z, v.w);
                *(float4*)(C + (long)m * ldc + n) = v;
            }
        }
}

// ---------------- small-N GEMM (emissions, N=66) ----------------
__global__ void gemm_nt(const float* __restrict__ A, const float* __restrict__ Bw,
                        float* __restrict__ C,
                        int M, int N, int K,
                        long sA, long sB, long sC, int ldc,
                        float scale,
                        const float* __restrict__ bias1, const float* __restrict__ bias2) {
    int bz = blockIdx.z;
    A  += (long)bz * sA;
    Bw += (long)bz * sB;
    C  += (long)bz * sC;
    int m0 = blockIdx.y * 64;
    int n0 = blockIdx.x * 64;
    __shared__ float As[16][68];
    __shared__ float Bs[16][68];
    int t = threadIdx.x;
    int tx = t & 15, ty = t >> 4;
    float acc[4][4];
    #pragma unroll
    for (int i = 0; i < 4; i++)
        #pragma unroll
        for (int j = 0; j < 4; j++) acc[i][j] = 0.f;
    int r = t >> 2;
    int cq = t & 3;
    for (int k0 = 0; k0 < K; k0 += 16) {
        float4 av = *(const float4*)(A + (long)(m0 + r) * K + k0 + cq * 4);
        As[cq * 4 + 0][r] = av.x; As[cq * 4 + 1][r] = av.y;
        As[cq * 4 + 2][r] = av.z; As[cq * 4 + 3][r] = av.w;
        float4 bv = make_float4(0.f, 0.f, 0.f, 0.f);
        if (n0 + r < N) bv = *(const float4*)(Bw + (long)(n0 + r) * K + k0 + cq * 4);
        Bs[cq * 4 + 0][r] = bv.x; Bs[cq * 4 + 1][r] = bv.y;
        Bs[cq * 4 + 2][r] = bv.z; Bs[cq * 4 + 3][r] = bv.w;
        __syncthreads();
        #pragma unroll
        for (int kk = 0; kk < 16; kk++) {
            float4 a  = *(const float4*)&As[kk][ty * 4];
            float4 bb = *(const float4*)&Bs[kk][tx * 4];
            acc[0][0] += a.x * bb.x; acc[0][1] += a.x * bb.y; acc[0][2] += a.x * bb.z; acc[0][3] += a.x * bb.w;
            acc[1][0] += a.y * bb.x; acc[1][1] += a.y * bb.y; acc[1][2] += a.y * bb.z; acc[1][3] += a.y * bb.w;
            acc[2][0] += a.z * bb.x; acc[2][1] += a.z * bb.y; acc[2][2] += a.z * bb.z; acc[2][3] += a.z * bb.w;
            acc[3][0] += a.w * bb.x; acc[3][1] += a.w * bb.y; acc[3][2] += a.w * bb.z; acc[3][3] += a.w * bb.w;
        }
        __syncthreads();
    }
    #pragma unroll
    for (int i = 0; i < 4; i++) {
        int m = m0 + ty * 4 + i;
        #pragma unroll
        for (int j = 0; j < 4; j++) {
            int n = n0 + tx * 4 + j;
            if (n < N) {
                float v = acc[i][j] * scale;
                if (bias1) v += bias1[n];
                if (bias2) v += bias2[n];
                C[(long)m * ldc + n] = v;
            }
        }
    }
}

// ---------------- softmax over rows of 256 ----------------
__global__ void softmax_rows(float* __restrict__ sc) {
    int row = blockIdx.x;
    int t = threadIdx.x;
    __shared__ float red[256];
    float v = sc[(long)row * 256 + t];
    red[t] = v;
    __syncthreads();
    for (int s = 128; s > 0; s >>= 1) {
        if (t < s) red[t] = fmaxf(red[t], red[t + s]);
        __syncthreads();
    }
    float m = red[0];
    __syncthreads();
    float e = expf(v - m);
    red[t] = e;
    __syncthreads();
    for (int s = 128; s > 0; s >>= 1) {
        if (t < s) red[t] += red[t + s];
        __syncthreads();
    }
    float inv = 1.f / red[0];
    sc[(long)row * 256 + t] = e * inv;
}

// =====================================================================
// Persistent BiLSTM layer: R15 body, barrier with 8-way parallel arrivals
// (8 counters per direction, 128B apart) + SINGLE poller per block.
// =====================================================================
__global__ void __launch_bounds__(256) lstm_layer2(
    const float* __restrict__ pre,   // [BT][2048]  dir*1024 + g*256 + u
    const float* __restrict__ whh,   // [2][1024][256]
    float* __restrict__ out)         // [BT][512]   dir*256 + u
{
    extern __shared__ float sm[];
    float* ws    = sm;                    // 4096 floats
    float* pre_s = sm + 4096;             // 1024 floats
    float4* hs4  = (float4*)(sm + 5120);  // 4160 float4: k4*65 + b

    int blk = blockIdx.x;
    int dir = blk >> 6;
    int u0 = (blk & 63) * 4;
    int tid = threadIdx.x;
    int uu = tid >> 6;
    int b = tid & 63;
    int u = u0 + uu;

    const float* wbase = whh + (long)dir * 1024 * 256;
    for (int i = tid; i < 4096; i += 256) {
        int uui = i >> 10;
        int g = (i >> 8) & 3;
        int k = i & 255;
        ws[i] = wbase[(long)(g * 256 + u0 + uui) * 256 + k];
    }

    float* hAd = g_hA + dir * BB * HH;
    float* hBd = g_hB + dir * BB * HH;

    const ulonglong2* hsu = (const ulonglong2*)hs4;
    const ulonglong2* wu2 = (const ulonglong2*)ws + uu * 256;

    int sb = tid >> 2, sg = tid & 3;
    const float* preB = pre + (long)sb * TT * 2048 + dir * 1024 + sg * 256 + u0;
    unsigned* myctr = &g_barM[(dir * 8 + (blk & 7)) * 32];
    const unsigned* ctrs = &g_barM[dir * 8 * 32];
    float c = 0.f;

    // prefetch pre for step 0
    int ts0 = dir ? (TT - 1) : 0;
    float4 preg = __ldcg((const float4*)(preB + (long)ts0 * 2048));

    for (int s = 0; s < TT; s++) {
        int tstep = dir ? (TT - 1 - s) : s;
        const float4* hin4 = (const float4*)((s & 1) ? hBd : hAd);
        float* hout = (s & 1) ? hAd : hBd;

        // stage pre slice from prefetched register
        pre_s[(sg * 4 + 0) * 64 + sb] = preg.x;
        pre_s[(sg * 4 + 1) * 64 + sb] = preg.y;
        pre_s[(sg * 4 + 2) * 64 + sb] = preg.z;
        pre_s[(sg * 4 + 3) * 64 + sb] = preg.w;
        // stage h[64][256] transposed into smem
        #pragma unroll
        for (int j = 0; j < 16; j++) {
            int idx = tid + j * 256;
            int hb = idx >> 6, k4 = idx & 63;
            float4 v = __ldcg(hin4 + hb * 64 + k4);
            hs4[k4 * 65 + hb] = v;
        }
        __syncthreads();

        // prefetch next step's pre (clamped; deterministic)
        {
            int snx = (s + 1 < TT) ? (s + 1) : s;
            int tnx = dir ? (TT - 1 - snx) : snx;
            preg = __ldcg((const float4*)(preB + (long)tnx * 2048));
        }

        float p0 = pre_s[(0 * 4 + uu) * 64 + b];
        float p1 = pre_s[(1 * 4 + uu) * 64 + b];
        float p2 = pre_s[(2 * 4 + uu) * 64 + b];
        float p3 = pre_s[(3 * 4 + uu) * 64 + b];

        unsigned long long ac0 = 0ull, ac1 = 0ull, ac2 = 0ull, ac3 = 0ull;
        #pragma unroll 8
        for (int k4 = 0; k4 < 64; k4++) {
            ulonglong2 hv = hsu[k4 * 65 + b];
            ulonglong2 w0 = wu2[k4];
            ulonglong2 w1 = wu2[64 + k4];
            ulonglong2 w2 = wu2[128 + k4];
            ulonglong2 w3 = wu2[192 + k4];
            ffma2(ac0, w0.x, hv.x); ffma2(ac0, w0.y, hv.y);
            ffma2(ac1, w1.x, hv.x); ffma2(ac1, w1.y, hv.y);
            ffma2(ac2, w2.x, hv.x); ffma2(ac2, w2.y, hv.y);
            ffma2(ac3, w3.x, hv.x); ffma2(ac3, w3.y, hv.y);
        }
        float lo, hi;
        unpk2(ac0, lo, hi); float a0 = p0 + lo + hi;
        unpk2(ac1, lo, hi); float a1 = p1 + lo + hi;
        unpk2(ac2, lo, hi); float a2 = p2 + lo + hi;
        unpk2(ac3, lo, hi); float a3 = p3 + lo + hi;

        float iv = 1.f / (1.f + expf(-a0));
        float fv = 1.f / (1.f + expf(-a1));
        float gv = tanhf(a2);
        float ov = 1.f / (1.f + expf(-a3));
        c = fv * c + iv * gv;
        float h = ov * tanhf(c);

        hout[b * HH + u] = h;

        if (s + 1 < TT) {
            __threadfence();        // h globally visible before arrive
            __syncthreads();        // all threads' h written

            if (tid == 0) atomicAdd(myctr, 1u);

            // overlap sequence-output store with the barrier wait
            out[((long)(b * TT + tstep)) * 512 + dir * 256 + u] = h;

            if (tid == 0) {
                unsigned target = (unsigned)(64 * (s + 1));
                for (;;) {
                    unsigned sum = 0;
                    #pragma unroll
                    for (int i = 0; i < 8; i++)
                        sum += *((volatile unsigned*)(ctrs + i * 32));
                    if (sum >= target) break;
                }
            }
            __syncthreads();
        } else {
            out[((long)(b * TT + tstep)) * 512 + dir * 256 + u] = h;
        }
    }
}

// ---------------- CRF NLL forward (one block per batch) ----------------
__global__ void crf_nll_kernel(const float* __restrict__ emit, const float* __restrict__ trans,
                               const int* __restrict__ tags) {
    int b = blockIdx.x;
    int t = threadIdx.x;
    __shared__ float tr[GG * GG];
    __shared__ float alpha[GG];
    for (int i = t; i < GG * GG; i += 128) tr[i] = trans[i];
    __syncthreads();
    if (t < GG) alpha[t] = tr[ST_START * GG + t] + emit[((long)b * TT) * GG + t];
    __syncthreads();
    for (int step = 1; step < TT; step++) {
        float anew = 0.f;
        if (t < GG) {
            float m = -1e30f;
            for (int i = 0; i < GG; i++) m = fmaxf(m, alpha[i] + tr[i * GG + t]);
            float sum = 0.f;
            for (int i = 0; i < GG; i++) sum += expf(alpha[i] + tr[i * GG + t] - m);
            anew = m + logf(sum) + emit[((long)b * TT + step) * GG + t];
        }
        __syncthreads();
        if (t < GG) alpha[t] = anew;
        __syncthreads();
    }
    if (t == 0) {
        float m = -1e30f;
        for (int j = 0; j < GG; j++) m = fmaxf(m, alpha[j] + tr[j * GG + ST_STOP]);
        float s = 0.f;
        for (int j = 0; j < GG; j++) s += expf(alpha[j] + tr[j * GG + ST_STOP] - m);
        float logZ = m + logf(s);
        const int* tg = tags + b * TT;
        float gold = tr[ST_START * GG + tg[0]];
        for (int k = 0; k < TT; k++) gold += emit[((long)b * TT + k) * GG + tg[k]];
        for (int k = 0; k < TT - 1; k++) gold += tr[tg[k] * GG + tg[k + 1]];
        gold += tr[tg[TT - 1] * GG + ST_STOP];
        g_losspart[b] = logZ - gold;
    }
}

__global__ void reduce_loss(float* __restrict__ out) {
    if (threadIdx.x == 0) {
        float s = 0.f;
        for (int b = 0; b < BB; b++) s += g_losspart[b];
        out[0] = s;
    }
}

// ---------------- Viterbi ----------------
__global__ void viterbi_kernel(const float* __restrict__ emit, const float* __restrict__ trans,
                               float* __restrict__ out) {
    int b = blockIdx.x;
    int t = threadIdx.x;
    __shared__ float tr[GG * GG];
    __shared__ float delta[GG];
    __shared__ unsigned char bp[TT][GG];
    for (int i = t; i < GG * GG; i += 128) tr[i] = trans[i];
    __syncthreads();
    if (t < GG) delta[t] = tr[ST_START * GG + t] + emit[((long)b * TT) * GG + t];
    __syncthreads();
    for (int step = 1; step < TT; step++) {
        float best = -1e30f;
        int arg = 0;
        if (t < GG) {
            for (int i = 0; i < GG; i++) {
                float v = delta[i] + tr[i * GG + t];
                if (v > best) { best = v; arg = i; }
            }
            best += emit[((long)b * TT + step) * GG + t];
        }
        __syncthreads();
        if (t < GG) { delta[t] = best; bp[step][t] = (unsigned char)arg; }
        __syncthreads();
    }
    if (t == 0) {
        float best = -1e30f;
        int tag = 0;
        for (int j = 0; j < GG; j++) {
            float v = delta[j] + tr[j * GG + ST_STOP];
            if (v > best) { best = v; tag = j; }
        }
        out[1 + b * TT + (TT - 1)] = (float)tag;
        for (int step = TT - 1; step >= 1; step--) {
            tag = bp[step][tag];
            out[1 + b * TT + step - 1] = (float)tag;
        }
    }
}

// ---------------- host driver ----------------
extern "C" void kernel_launch(void* const* d_in, const int* in_sizes, int n_in,
                              void* d_out, int out_size) {
    const int*   bw    = (const int*)d_in[0];
    const int*   bi    = (const int*)d_in[1];
    const int*   bc    = (const int*)d_in[3];
    const int*   blx   = (const int*)d_in[6];
    const int*   blab  = (const int*)d_in[7];
    const float* cemb  = (const float*)d_in[8];
    const float* wemb  = (const float*)d_in[9];
    const float* lemb  = (const float*)d_in[10];
    const float* iemb  = (const float*)d_in[11];
    const float* convw = (const float*)d_in[12];
    const float* convb = (const float*)d_in[13];
    const float* wih   = (const float*)d_in[14];
    const float* whh   = (const float*)d_in[15];
    const float* bih   = (const float*)d_in[16];
    const float* bhh   = (const float*)d_in[17];
    const float* pw    = (const float*)d_in[18];
    const float* pb    = (const float*)d_in[19];
    const float* trans = (const float*)d_in[20];
    float* out = (float*)d_out;

    float *p_cwin, *p_cwt, *p_q, *p_kv, *p_sc, *p_x0, *p_x1, *p_x2, *p_pre, *p_emit;
    cudaGetSymbolAddress((void**)&p_cwin, g_cwin);
    cudaGetSymbolAddress((void**)&p_cwt,  g_cwt);
    cudaGetSymbolAddress((void**)&p_q,    g_q);
    cudaGetSymbolAddress((void**)&p_kv,   g_kv);
    cudaGetSymbolAddress((void**)&p_sc,   g_sc);
    cudaGetSymbolAddress((void**)&p_x0,   g_x0);
    cudaGetSymbolAddress((void**)&p_x1,   g_x1);
    cudaGetSymbolAddress((void**)&p_x2,   g_x2);
    cudaGetSymbolAddress((void**)&p_pre,  g_pre);
    cudaGetSymbolAddress((void**)&p_emit, g_emit);

    const int lstm_smem = (4096 + 1024 + 4160 * 4) * 4;  // 87040 B
    cudaFuncSetAttribute(lstm_layer2, cudaFuncAttributeMaxDynamicSharedMemorySize, lstm_smem);

    const float inv_temp = 1.0f / sqrtf(128.0f);

    // 1) inputs assembly
    transpose_convw<<<(HCC * 384 + 255) / 256, 256>>>(convw);
    build_cwin<<<BT, 128>>>(bc, cemb);
    build_tails<<<BT, 128>>>(bw, bi, blx, wemb, lemb, iemb);

    // 2) char CNN as GEMM
    gemm128_nt<<<dim3(3, 128, 1), 256>>>(p_cwin, p_cwt, p_q,
                                         BT, 384, 384, 0, 0, 0, 512,
                                         1.0f, convb, nullptr);

    // 3) attention scores
    gemm128_nt<<<dim3(2, 2, BB), 256>>>(p_q, p_kv, p_sc,
                                        256, 256, 512,
                                        (long)TT * 512, (long)TT * 512, (long)TT * 256, 256,
                                        inv_temp, nullptr, nullptr);
    softmax_rows<<<BT, 256>>>(p_sc);

    // 4) context
    gemm128_nn<<<dim3(4, 2, BB), 256>>>(p_sc, p_kv, p_x0,
                                        256, 512, 256, 512, 512,
                                        (long)TT * 256, (long)TT * 512, (long)TT * 512);

    // 5) two BiLSTM layers
    for (int l = 0; l < 2; l++) {
        const float* xin  = (l == 0) ? p_x0 : p_x1;
        float*       xout = (l == 0) ? p_x1 : p_x2;
        gemm128_nt<<<dim3(16, 128, 1), 256>>>(xin, wih + (long)l * 2 * H44 * LHH, p_pre,
                                              BT, 2048, 512, 0, 0, 0, 2048,
                                              1.0f, bih + l * 2 * H44, bhh + l * 2 * H44);
        lstm_init<<<128, 256>>>();
        lstm_layer2<<<LSTM_BLOCKS, 256, lstm_smem>>>(p_pre, whh + (long)l * 2 * H44 * HH, xout);
    }

    // 6) emissions
    gemm_nt<<<dim3(2, 256, 1), 256>>>(p_x2, pw, p_emit,
                                      BT, GG, 512, 0, 0, 0, GG,
                                      1.0f, pb, nullptr);

    // 7) CRF NLL + Viterbi
    crf_nll_kernel<<<BB, 128>>>(p_emit, trans, blab);
    reduce_loss<<<1, 32>>>(out);
    viterbi_kernel<<<BB, 128>>>(p_emit, trans, out);
}